// round 13
// baseline (speedup 1.0000x reference)
#include <cuda_runtime.h>
#include <cuda_fp16.h>
#include <math.h>
#include <stdint.h>

#define BB 2
#define TT 2048
#define HH 16
#define DD 64
#define MM 1024

// Persistent scratch (device globals)
__device__ float g_Ap[8 * HH * DD * DD];        // k-split partials for A
__device__ __half g_Ah[HH * DD * DD];           // A split hi  [h][d][d']
__device__ __half g_Al[HH * DD * DD];           // A split lo
__device__ __half g_xh[BB * HH * TT * DD];      // x per-head, fp16 hi  [bh][t][64]
__device__ __half g_xl[BB * HH * TT * DD];      // x per-head, fp16 lo
__device__ __half g_zh[BB * TT * MM];           // attn out, fp16 hi    [b][t][1024]
__device__ __half g_zl[BB * TT * MM];
__device__ __half g_Uh[MM * MM];                // U = Wv@Wo, fp16 (single)

__device__ __forceinline__ uint32_t pkh(float a, float b) {
    __half2 t = __floats2half2_rn(a, b);
    return *reinterpret_cast<uint32_t*>(&t);
}
__device__ __forceinline__ float hfh(float x) {
    return __half2float(__float2half_rn(x));
}
__device__ __forceinline__ float ex2f(float x) {
    float y;
    asm("ex2.approx.ftz.f32 %0, %1;" : "=f"(y) : "f"(x));
    return y;
}
__device__ __forceinline__ void cpa(uint32_t d, const void* s) {
    asm volatile("cp.async.cg.shared.global [%0], [%1], 16;" :: "r"(d), "l"(s));
}
#define CPCOMMIT() asm volatile("cp.async.commit_group;")
#define CPWAIT1() asm volatile("cp.async.wait_group 1;")
#define CPWAIT0() asm volatile("cp.async.wait_group 0;")

#define LDSM4(R, A) asm volatile( \
    "ldmatrix.sync.aligned.m8n8.x4.shared.b16 {%0,%1,%2,%3},[%4];" \
    : "=r"((R)[0]), "=r"((R)[1]), "=r"((R)[2]), "=r"((R)[3]) : "r"(A))
#define LDSM4T(R, A) asm volatile( \
    "ldmatrix.sync.aligned.m8n8.x4.trans.shared.b16 {%0,%1,%2,%3},[%4];" \
    : "=r"((R)[0]), "=r"((R)[1]), "=r"((R)[2]), "=r"((R)[3]) : "r"(A))
#define MMAH(D, A, B0, B1) asm volatile( \
    "mma.sync.aligned.m16n8k16.row.col.f32.f16.f16.f32 " \
    "{%0,%1,%2,%3},{%4,%5,%6,%7},{%8,%9},{%0,%1,%2,%3};" \
    : "+f"((D)[0]), "+f"((D)[1]), "+f"((D)[2]), "+f"((D)[3]) \
    : "r"((A)[0]), "r"((A)[1]), "r"((A)[2]), "r"((A)[3]), "r"(B0), "r"(B1))

// ---------------------------------------------------------------------------
// Kernel 0: split x into per-head fp16 hi/lo, layout [bh][t][64]
// ---------------------------------------------------------------------------
__global__ void __launch_bounds__(256) splitX(const float* __restrict__ x) {
    int fi = blockIdx.x * 256 + threadIdx.x;
    size_t e = (size_t)fi * 4;
    int b = (int)(e / ((size_t)TT * MM));
    size_t rem = e % ((size_t)TT * MM);
    int t = (int)(rem / MM);
    int col = (int)(rem % MM);
    int h = col >> 6, c = col & 63;
    float4 v = *(const float4*)(x + e);
    float hx = hfh(v.x), hy = hfh(v.y), hz = hfh(v.z), hw = hfh(v.w);
    size_t di = (((size_t)(b * 16 + h) * TT + t) * 64 + c);
    *(uint32_t*)((char*)g_xh + di * 2) = pkh(hx, hy);
    *(uint32_t*)((char*)g_xh + di * 2 + 4) = pkh(hz, hw);
    *(uint32_t*)((char*)g_xl + di * 2) = pkh(v.x - hx, v.y - hy);
    *(uint32_t*)((char*)g_xl + di * 2 + 4) = pkh(v.z - hz, v.w - hw);
}

// ---------------------------------------------------------------------------
// Kernel 1a: partial A; grid (16 h, 8 kseg)
// ---------------------------------------------------------------------------
__global__ void __launch_bounds__(256) computeApart(const float* __restrict__ Wq,
                                                    const float* __restrict__ Wk) {
    const int h = blockIdx.x, ks = blockIdx.y, tid = threadIdx.x;
    const int tx = tid & 15, ty = tid >> 4;
    __shared__ float wqs[64 * 65];
    __shared__ float wks[64 * 65];
    float acc[4][4];
#pragma unroll
    for (int i = 0; i < 4; i++)
#pragma unroll
        for (int j = 0; j < 4; j++) acc[i][j] = 0.f;
    const float* wqh = Wq + (size_t)h * DD * MM;
    const float* wkh = Wk + (size_t)h * DD * MM;
    for (int m0 = ks * 128; m0 < ks * 128 + 128; m0 += 64) {
        __syncthreads();
#pragma unroll
        for (int c = 0; c < 4; c++) {
            int fi = tid + c * 256, i = fi >> 4, q = fi & 15;
            float4 a = *(const float4*)(wqh + i * MM + m0 + q * 4);
            wqs[i * 65 + q * 4 + 0] = a.x; wqs[i * 65 + q * 4 + 1] = a.y;
            wqs[i * 65 + q * 4 + 2] = a.z; wqs[i * 65 + q * 4 + 3] = a.w;
            float4 b = *(const float4*)(wkh + i * MM + m0 + q * 4);
            wks[i * 65 + q * 4 + 0] = b.x; wks[i * 65 + q * 4 + 1] = b.y;
            wks[i * 65 + q * 4 + 2] = b.z; wks[i * 65 + q * 4 + 3] = b.w;
        }
        __syncthreads();
        for (int m = 0; m < 64; m++) {
            float a[4], b[4];
#pragma unroll
            for (int i = 0; i < 4; i++) a[i] = wqs[(ty * 4 + i) * 65 + m];
#pragma unroll
            for (int j = 0; j < 4; j++) b[j] = wks[(tx * 4 + j) * 65 + m];
#pragma unroll
            for (int i = 0; i < 4; i++)
#pragma unroll
                for (int j = 0; j < 4; j++) acc[i][j] += a[i] * b[j];
        }
    }
    float* o = g_Ap + (size_t)ks * (HH * DD * DD) + h * DD * DD;
#pragma unroll
    for (int i = 0; i < 4; i++)
#pragma unroll
        for (int j = 0; j < 4; j++)
            o[(ty * 4 + i) * DD + tx * 4 + j] = acc[i][j];
}

// Kernel 1b: reduce partials, scale, split to fp16 hi/lo
__global__ void __launch_bounds__(256) reduceA() {
    int i = blockIdx.x * 256 + threadIdx.x;
    float s = 0.f;
#pragma unroll
    for (int k = 0; k < 8; k++) s += g_Ap[(size_t)k * (HH * DD * DD) + i];
    s *= (0.125f * 1.4426950408889634f);
    float hv = hfh(s);
    g_Ah[i] = __float2half_rn(s);
    g_Al[i] = __float2half_rn(s - hv);
}

// ---------------------------------------------------------------------------
// Kernel 2: U = Wv_h @ Wo_h — Wv fp16-split x Wo fp16-single, full K=1024,
// direct fp16 output. grid (8 col-tiles, 16 h), 256 threads.
// ---------------------------------------------------------------------------
#define CU_SMEM 37888

__global__ void __launch_bounds__(256, 1) computeUTC(const float* __restrict__ Wv,
                                                     const float* __restrict__ Wo) {
    extern __shared__ __align__(16) char sm[];
    const uint32_t sb = (uint32_t)__cvta_generic_to_shared(sm);
    const uint32_t AH[2] = {0u, 18944u}, AL[2] = {5120u, 24064u};
    const uint32_t BH[2] = {10240u, 29184u};
    const int tid = threadIdx.x, lane = tid & 31, w = tid >> 5;
    const int h = blockIdx.y, col0 = blockIdx.x * 128;
    const int wr = (w & 3) * 16, wc = (w >> 2) * 64;
    const float* wvh = Wv + (size_t)h * DD * MM;
    const float* woh = Wo + (size_t)h * MM * MM;

#pragma unroll
    for (int c = 0; c < 2; c++) {
        int idx = tid + c * 256;
        int r = idx >> 3, kq = idx & 7;
        float4 v = *(const float4*)(wvh + (size_t)r * MM + kq * 4);
        float hx = hfh(v.x), hy = hfh(v.y), hz = hfh(v.z), hw = hfh(v.w);
        uint32_t o = (uint32_t)(r * 80 + kq * 8);
        *(uint32_t*)(sm + AH[0] + o) = pkh(hx, hy);
        *(uint32_t*)(sm + AH[0] + o + 4) = pkh(hz, hw);
        *(uint32_t*)(sm + AL[0] + o) = pkh(v.x - hx, v.y - hy);
        *(uint32_t*)(sm + AL[0] + o + 4) = pkh(v.z - hz, v.w - hw);
    }
#pragma unroll
    for (int c = 0; c < 4; c++) {
        int fi = tid + c * 256;
        int kk = fi >> 5, q = fi & 31;
        float4 v = *(const float4*)(woh + (size_t)kk * MM + col0 + q * 4);
        uint32_t o = (uint32_t)(kk * 272 + q * 8);
        *(uint32_t*)(sm + BH[0] + o) = pkh(v.x, v.y);
        *(uint32_t*)(sm + BH[0] + o + 4) = pkh(v.z, v.w);
    }
    __syncthreads();

    float acc[8][4];
#pragma unroll
    for (int j = 0; j < 8; j++)
        acc[j][0] = acc[j][1] = acc[j][2] = acc[j][3] = 0.f;

    const uint32_t aro = (uint32_t)((wr + (lane & 15)) * 80 + ((lane >> 4) << 3) * 2);
    const uint32_t bro = (uint32_t)((lane & 15) * 272 + (wc + ((lane >> 4) << 3)) * 2);

    for (int it = 0; it < 32; it++) {
        const int cur = it & 1, nx = cur ^ 1;
        float4 pv[2], po[4];
        if (it < 31) {
            int m0 = (it + 1) * 32;
#pragma unroll
            for (int c = 0; c < 2; c++) {
                int idx = tid + c * 256;
                int r = idx >> 3, kq = idx & 7;
                pv[c] = *(const float4*)(wvh + (size_t)r * MM + m0 + kq * 4);
            }
#pragma unroll
            for (int c = 0; c < 4; c++) {
                int fi = tid + c * 256;
                int kk = fi >> 5, q = fi & 31;
                po[c] = *(const float4*)(woh + (size_t)(m0 + kk) * MM + col0 + q * 4);
            }
        }

#pragma unroll
        for (int kk = 0; kk < 2; kk++) {
            uint32_t ah4[4], al4[4];
            LDSM4(ah4, sb + AH[cur] + aro + kk * 32);
            LDSM4(al4, sb + AL[cur] + aro + kk * 32);
#pragma unroll
            for (int jp = 0; jp < 4; jp++) {
                uint32_t off = (uint32_t)(kk * 4352 + jp * 32);
                uint32_t bh4[4];
                LDSM4T(bh4, sb + BH[cur] + bro + off);
                MMAH(acc[2 * jp], ah4, bh4[0], bh4[1]);
                MMAH(acc[2 * jp], al4, bh4[0], bh4[1]);
                MMAH(acc[2 * jp + 1], ah4, bh4[2], bh4[3]);
                MMAH(acc[2 * jp + 1], al4, bh4[2], bh4[3]);
            }
        }

        if (it < 31) {
#pragma unroll
            for (int c = 0; c < 2; c++) {
                int idx = tid + c * 256;
                int r = idx >> 3, kq = idx & 7;
                float4 v = pv[c];
                float hx = hfh(v.x), hy = hfh(v.y), hz = hfh(v.z), hw = hfh(v.w);
                uint32_t o = (uint32_t)(r * 80 + kq * 8);
                *(uint32_t*)(sm + AH[nx] + o) = pkh(hx, hy);
                *(uint32_t*)(sm + AH[nx] + o + 4) = pkh(hz, hw);
                *(uint32_t*)(sm + AL[nx] + o) = pkh(v.x - hx, v.y - hy);
                *(uint32_t*)(sm + AL[nx] + o + 4) = pkh(v.z - hz, v.w - hw);
            }
#pragma unroll
            for (int c = 0; c < 4; c++) {
                int fi = tid + c * 256;
                int kk = fi >> 5, q = fi & 31;
                float4 v = po[c];
                uint32_t o = (uint32_t)(kk * 272 + q * 8);
                *(uint32_t*)(sm + BH[nx] + o) = pkh(v.x, v.y);
                *(uint32_t*)(sm + BH[nx] + o + 4) = pkh(v.z, v.w);
            }
        }
        __syncthreads();
    }

    // write fp16 U directly
    int r = lane >> 2, cc = (lane & 3) * 2;
    int row = h * 64 + wr + r;
#pragma unroll
    for (int j = 0; j < 8; j++) {
        int gc = col0 + wc + 8 * j + cc;
        *(uint32_t*)((char*)g_Uh + ((size_t)row * MM + gc) * 2) =
            pkh(acc[j][0], acc[j][1]);
        *(uint32_t*)((char*)g_Uh + ((size_t)(row + 8) * MM + gc) * 2) =
            pkh(acc[j][2], acc[j][3]);
    }
}

// ---------------------------------------------------------------------------
// Kernel 4: flash attention — 64-key tiles, K hi-only, 3 CTAs/SM (unchanged)
// ---------------------------------------------------------------------------
#define FL_SMEM 36864

__global__ void __launch_bounds__(128, 3) flashTC() {
    extern __shared__ __align__(16) char sm[];
    const uint32_t sb = (uint32_t)__cvta_generic_to_shared(sm);
    const uint32_t KH0 = 0u, KH1 = 9216u;
    const uint32_t XH = 0u, XL = 9216u, AHs = 18432u, ALs = 27648u;
    const int tid = threadIdx.x, lane = tid & 31, w = tid >> 5;
    const int t0 = blockIdx.x * 64, bh = blockIdx.y;
    const int b = bh >> 4, h = bh & 15;

    const __half* xh = g_xh + (size_t)bh * TT * 64;
    const __half* xl = g_xl + (size_t)bh * TT * 64;

    {
        const __half* Ah = g_Ah + (size_t)h * DD * DD;
        const __half* Al = g_Al + (size_t)h * DD * DD;
#pragma unroll
        for (int c = 0; c < 4; c++) {
            int idx = tid + c * 128;
            int r = idx >> 3, ch = idx & 7;
            cpa(sb + XH + r * 144 + ch * 16, xh + (size_t)(t0 + r) * 64 + ch * 8);
            cpa(sb + XL + r * 144 + ch * 16, xl + (size_t)(t0 + r) * 64 + ch * 8);
            cpa(sb + AHs + r * 144 + ch * 16, Ah + (size_t)r * 64 + ch * 8);
            cpa(sb + ALs + r * 144 + ch * 16, Al + (size_t)r * 64 + ch * 8);
        }
        CPCOMMIT();
        CPWAIT0();
        __syncthreads();
    }

    uint32_t qh[4][4], ql[4][4];
    {
        float QS[8][4];
#pragma unroll
        for (int j = 0; j < 8; j++) { QS[j][0] = QS[j][1] = QS[j][2] = QS[j][3] = 0.f; }
        uint32_t xro = (uint32_t)((16 * w + (lane & 15)) * 144 + ((lane >> 4) << 3) * 2);
        uint32_t aro = (uint32_t)((lane & 15) * 144 + ((lane >> 4) << 3) * 2);
#pragma unroll
        for (int kk = 0; kk < 4; kk++) {
            uint32_t xh4[4], xl4[4];
            LDSM4(xh4, sb + XH + xro + kk * 32);
            LDSM4(xl4, sb + XL + xro + kk * 32);
#pragma unroll
            for (int jp = 0; jp < 4; jp++) {
                uint32_t off = (uint32_t)(kk * 2304 + jp * 32);
                uint32_t bh4[4], bl4[4];
                LDSM4T(bh4, sb + AHs + aro + off);
                LDSM4T(bl4, sb + ALs + aro + off);
                MMAH(QS[2 * jp], xh4, bh4[0], bh4[1]);
                MMAH(QS[2 * jp], xh4, bl4[0], bl4[1]);
                MMAH(QS[2 * jp], xl4, bh4[0], bh4[1]);
                MMAH(QS[2 * jp + 1], xh4, bh4[2], bh4[3]);
                MMAH(QS[2 * jp + 1], xh4, bl4[2], bl4[3]);
                MMAH(QS[2 * jp + 1], xl4, bh4[2], bh4[3]);
            }
        }
#pragma unroll
        for (int j = 0; j < 8; j++) {
            float q0 = QS[j][0], q1 = QS[j][1], q2 = QS[j][2], q3 = QS[j][3];
            float h0 = hfh(q0), h1 = hfh(q1), h2 = hfh(q2), h3 = hfh(q3);
            int kkq = j >> 1, ps = (j & 1) << 1;
            qh[kkq][ps] = pkh(h0, h1);
            qh[kkq][ps + 1] = pkh(h2, h3);
            ql[kkq][ps] = pkh(q0 - h0, q1 - h1);
            ql[kkq][ps + 1] = pkh(q2 - h2, q3 - h3);
        }
    }
    __syncthreads();

#pragma unroll
    for (int c = 0; c < 4; c++) {
        int idx = tid + c * 128;
        int r = idx >> 3, ch = idx & 7;
        cpa(sb + KH0 + r * 144 + ch * 16, xh + (size_t)r * 64 + ch * 8);
    }
    CPCOMMIT();

    float acc[8][4];
    float mrow0 = -INFINITY, mrow1 = -INFINITY, lrow0 = 0.f, lrow1 = 0.f;
#pragma unroll
    for (int j = 0; j < 8; j++) { acc[j][0] = acc[j][1] = acc[j][2] = acc[j][3] = 0.f; }

    const uint32_t rbase1 = sb + (uint32_t)(((lane & 7) + ((lane >> 4) << 3)) * 144 +
                                            (((lane >> 3) & 1) << 3) * 2);
    const uint32_t rbase2 = sb + (uint32_t)((lane & 15) * 144 + ((lane >> 4) << 3) * 2);

    for (int it = 0; it < 32; it++) {
        const uint32_t curH = (it & 1) ? KH1 : KH0;
        const uint32_t nxtH = (it & 1) ? KH0 : KH1;

        __syncthreads();
        if (it < 31) {
            int s0 = (it + 1) * 64;
#pragma unroll
            for (int c = 0; c < 4; c++) {
                int idx = tid + c * 128;
                int r = idx >> 3, ch = idx & 7;
                cpa(sb + nxtH + r * 144 + ch * 16, xh + (size_t)(s0 + r) * 64 + ch * 8);
            }
            CPCOMMIT();
            CPWAIT1();
        } else {
            CPWAIT0();
        }
        __syncthreads();

        float S[8][4];
#pragma unroll
        for (int j = 0; j < 8; j++) { S[j][0] = S[j][1] = S[j][2] = S[j][3] = 0.f; }
#pragma unroll
        for (int jp = 0; jp < 4; jp++) {
#pragma unroll
            for (int kk = 0; kk < 4; kk++) {
                uint32_t off = (uint32_t)(jp * 2304 + kk * 32);
                uint32_t bh4[4];
                LDSM4(bh4, rbase1 + curH + off);
                MMAH(S[2 * jp], qh[kk], bh4[0], bh4[1]);
                MMAH(S[2 * jp], ql[kk], bh4[0], bh4[1]);
                MMAH(S[2 * jp + 1], qh[kk], bh4[2], bh4[3]);
                MMAH(S[2 * jp + 1], ql[kk], bh4[2], bh4[3]);
            }
        }

        float mx0 = -INFINITY, mx1 = -INFINITY;
#pragma unroll
        for (int j = 0; j < 8; j++) {
            mx0 = fmaxf(mx0, fmaxf(S[j][0], S[j][1]));
            mx1 = fmaxf(mx1, fmaxf(S[j][2], S[j][3]));
        }
        mx0 = fmaxf(mx0, __shfl_xor_sync(0xffffffffu, mx0, 1));
        mx0 = fmaxf(mx0, __shfl_xor_sync(0xffffffffu, mx0, 2));
        mx1 = fmaxf(mx1, __shfl_xor_sync(0xffffffffu, mx1, 1));
        mx1 = fmaxf(mx1, __shfl_xor_sync(0xffffffffu, mx1, 2));
        float mn0 = fmaxf(mrow0, mx0), mn1 = fmaxf(mrow1, mx1);
        float sc0 = ex2f(mrow0 - mn0), sc1 = ex2f(mrow1 - mn1);
        mrow0 = mn0; mrow1 = mn1;

        uint32_t php[4][4];
        float rs0 = 0.f, rs1 = 0.f;
#pragma unroll
        for (int j = 0; j < 8; j++) {
            float p0 = ex2f(S[j][0] - mn0), p1 = ex2f(S[j][1] - mn0);
            float p2 = ex2f(S[j][2] - mn1), p3 = ex2f(S[j][3] - mn1);
            rs0 += p0 + p1; rs1 += p2 + p3;
            int ss = j >> 1, ps = (j & 1) << 1;
            php[ss][ps] = pkh(p0, p1);
            php[ss][ps + 1] = pkh(p2, p3);
        }
        rs0 += __shfl_xor_sync(0xffffffffu, rs0, 1);
        rs0 += __shfl_xor_sync(0xffffffffu, rs0, 2);
        rs1 += __shfl_xor_sync(0xffffffffu, rs1, 1);
        rs1 += __shfl_xor_sync(0xffffffffu, rs1, 2);
        lrow0 = lrow0 * sc0 + rs0;
        lrow1 = lrow1 * sc1 + rs1;
#pragma unroll
        for (int j = 0; j < 8; j++) {
            acc[j][0] *= sc0; acc[j][1] *= sc0; acc[j][2] *= sc1; acc[j][3] *= sc1;
        }

#pragma unroll
        for (int ss = 0; ss < 4; ss++) {
#pragma unroll
            for (int jp = 0; jp < 4; jp++) {
                uint32_t off = (uint32_t)(ss * 2304 + jp * 32);
                uint32_t vh4[4];
                LDSM4T(vh4, rbase2 + curH + off);
                MMAH(acc[2 * jp], php[ss], vh4[0], vh4[1]);
                MMAH(acc[2 * jp + 1], php[ss], vh4[2], vh4[3]);
            }
        }
    }

    float inv0 = 1.f / lrow0, inv1 = 1.f / lrow1;
    int r0 = lane >> 2, c0 = (lane & 3) * 2;
    size_t rowA = ((size_t)b * TT + t0 + 16 * w + r0) * MM + h * 64;
    size_t rowB = rowA + 8 * MM;
#pragma unroll
    for (int j = 0; j < 8; j++) {
        float o0 = acc[j][0] * inv0, o1 = acc[j][1] * inv0;
        float o2 = acc[j][2] * inv1, o3 = acc[j][3] * inv1;
        float h0 = hfh(o0), h1 = hfh(o1), h2 = hfh(o2), h3 = hfh(o3);
        size_t ia = rowA + 8 * j + c0, ib = rowB + 8 * j + c0;
        *(uint32_t*)((char*)g_zh + ia * 2) = pkh(h0, h1);
        *(uint32_t*)((char*)g_zl + ia * 2) = pkh(o0 - h0, o1 - h1);
        *(uint32_t*)((char*)g_zh + ib * 2) = pkh(h2, h3);
        *(uint32_t*)((char*)g_zl + ib * 2) = pkh(o2 - h2, o3 - h3);
    }
}

// ---------------------------------------------------------------------------
// Kernel 5: out = z @ U + bo — 256 threads, tile 128x128, k-chunk 64, 2 CTA/SM
// warp w: rows 32*(w&3), cols 64*(w>>2)
// ---------------------------------------------------------------------------
#define GO_SMEM 108544

__global__ void __launch_bounds__(256, 2) gemmOutTC(const float* __restrict__ bo,
                                                    float* __restrict__ out) {
    extern __shared__ __align__(16) char sm[];
    const uint32_t sb = (uint32_t)__cvta_generic_to_shared(sm);
    const uint32_t ZH[2] = {0u, 54272u}, ZL[2] = {18432u, 72704u};
    const uint32_t UH[2] = {36864u, 91136u};
    const int tid = threadIdx.x, lane = tid & 31, w = tid >> 5;
    const int col0 = blockIdx.x * 128, row0 = blockIdx.y * 128;
    const int wr = (w & 3) * 32, wc = (w >> 2) * 64;

#pragma unroll
    for (int c = 0; c < 4; c++) {
        int idx = tid + c * 256;           // 0..1023
        int r = idx >> 3, ch = idx & 7;
        cpa(sb + ZH[0] + r * 144 + ch * 16, g_zh + (size_t)(row0 + r) * MM + ch * 8);
        cpa(sb + ZL[0] + r * 144 + ch * 16, g_zl + (size_t)(row0 + r) * MM + ch * 8);
        int kk = idx >> 4, q = idx & 15;
        cpa(sb + UH[0] + kk * 272 + q * 16, g_Uh + (size_t)kk * MM + col0 + q * 8);
    }
    CPCOMMIT();

    float acc[2][8][4];
#pragma unroll
    for (int rb = 0; rb < 2; rb++)
#pragma unroll
        for (int j = 0; j < 8; j++)
            acc[rb][j][0] = acc[rb][j][1] = acc[rb][j][2] = acc[rb][j][3] = 0.f;

    const uint32_t aro = (uint32_t)((wr + (lane & 15)) * 144 + ((lane >> 4) << 3) * 2);
    const uint32_t bro = (uint32_t)((lane & 15) * 272 + (wc + ((lane >> 4) << 3)) * 2);

    for (int it = 0; it < 16; it++) {
        const int cur = it & 1, nx = cur ^ 1;
        __syncthreads();
        if (it < 15) {
            int k0 = (it + 1) * 64;
#pragma unroll
            for (int c = 0; c < 4; c++) {
                int idx = tid + c * 256;
                int r = idx >> 3, ch = idx & 7;
                cpa(sb + ZH[nx] + r * 144 + ch * 16,
                    g_zh + (size_t)(row0 + r) * MM + k0 + ch * 8);
                cpa(sb + ZL[nx] + r * 144 + ch * 16,
                    g_zl + (size_t)(row0 + r) * MM + k0 + ch * 8);
                int kk = idx >> 4, q = idx & 15;
                cpa(sb + UH[nx] + kk * 272 + q * 16,
                    g_Uh + (size_t)(k0 + kk) * MM + col0 + q * 8);
            }
            CPCOMMIT();
            CPWAIT1();
        } else {
            CPWAIT0();
        }
        __syncthreads();

#pragma unroll
        for (int kk = 0; kk < 4; kk++) {
            uint32_t ah0[4], al0[4], ah1[4], al1[4];
            LDSM4(ah0, sb + ZH[cur] + aro + kk * 32);
            LDSM4(al0, sb + ZL[cur] + aro + kk * 32);
            LDSM4(ah1, sb + ZH[cur] + aro + 2304 + kk * 32);
            LDSM4(al1, sb + ZL[cur] + aro + 2304 + kk * 32);
#pragma unroll
            for (int jp = 0; jp < 4; jp++) {
                uint32_t off = (uint32_t)(kk * 4352 + jp * 32);
                uint32_t bh4[4];
                LDSM4T(bh4, sb + UH[cur] + bro + off);
                MMAH(acc[0][2 * jp], ah0, bh4[0], bh4[1]);
                MMAH(acc[0][2 * jp], al0, bh4[0], bh4[1]);
                MMAH(acc[0][2 * jp + 1], ah0, bh4[2], bh4[3]);
                MMAH(acc[0][2 * jp + 1], al0, bh4[2], bh4[3]);
                MMAH(acc[1][2 * jp], ah1, bh4[0], bh4[1]);
                MMAH(acc[1][2 * jp], al1, bh4[0], bh4[1]);
                MMAH(acc[1][2 * jp + 1], ah1, bh4[2], bh4[3]);
                MMAH(acc[1][2 * jp + 1], al1, bh4[2], bh4[3]);
            }
        }
    }

    int r = lane >> 2, cc = (lane & 3) * 2;
#pragma unroll
    for (int rb = 0; rb < 2; rb++) {
        int gr = row0 + wr + rb * 16 + r;
#pragma unroll
        for (int j = 0; j < 8; j++) {
            int gc = col0 + wc + 8 * j + cc;
            float b0v = bo[gc], b1v = bo[gc + 1];
            *(float2*)(out + (size_t)gr * MM + gc) =
                make_float2(acc[rb][j][0] + b0v, acc[rb][j][1] + b1v);
            *(float2*)(out + (size_t)(gr + 8) * MM + gc) =
                make_float2(acc[rb][j][2] + b0v, acc[rb][j][3] + b1v);
        }
    }
}

// ---------------------------------------------------------------------------
extern "C" void kernel_launch(void* const* d_in, const int* in_sizes, int n_in,
                              void* d_out, int out_size) {
    const float* x  = (const float*)d_in[0];
    const float* Wq = (const float*)d_in[1];
    const float* Wk = (const float*)d_in[2];
    const float* Wv = (const float*)d_in[3];
    const float* Wo = (const float*)d_in[4];
    const float* bo = (const float*)d_in[5];
    float* out = (float*)d_out;

    cudaFuncSetAttribute(flashTC, cudaFuncAttributeMaxDynamicSharedMemorySize, FL_SMEM);
    cudaFuncSetAttribute(gemmOutTC, cudaFuncAttributeMaxDynamicSharedMemorySize, GO_SMEM);
    cudaFuncSetAttribute(computeUTC, cudaFuncAttributeMaxDynamicSharedMemorySize, CU_SMEM);

    splitX<<<4096, 256>>>(x);
    computeApart<<<dim3(16, 8), 256>>>(Wq, Wk);
    reduceA<<<256, 256>>>();
    computeUTC<<<dim3(8, 16), 256, CU_SMEM>>>(Wv, Wo);
    flashTC<<<dim3(TT / 64, BB * HH), 128, FL_SMEM>>>();
    gemmOutTC<<<dim3(MM / 128, (BB * TT) / 128), 256, GO_SMEM>>>(bo, out);
}

// round 14
// speedup vs baseline: 1.0089x; 1.0089x over previous
#include <cuda_runtime.h>
#include <cuda_fp16.h>
#include <math.h>
#include <stdint.h>

#define BB 2
#define TT 2048
#define HH 16
#define DD 64
#define MM 1024

// Persistent scratch (device globals)
__device__ float g_Ap[8 * HH * DD * DD];        // k-split partials for A
__device__ __half g_Ah[HH * DD * DD];           // A split hi  [h][d][d']
__device__ __half g_Al[HH * DD * DD];           // A split lo
__device__ __half g_xh[BB * HH * TT * DD];      // x per-head, fp16 hi  [bh][t][64]
__device__ __half g_xl[BB * HH * TT * DD];      // x per-head, fp16 lo
__device__ __half g_zh[BB * TT * MM];           // attn out, fp16 hi    [b][t][1024]
__device__ __half g_zl[BB * TT * MM];
__device__ __half g_Uh[MM * MM];                // U = Wv@Wo, fp16 (single)

__device__ __forceinline__ uint32_t pkh(float a, float b) {
    __half2 t = __floats2half2_rn(a, b);
    return *reinterpret_cast<uint32_t*>(&t);
}
__device__ __forceinline__ float hfh(float x) {
    return __half2float(__float2half_rn(x));
}
__device__ __forceinline__ float ex2f(float x) {
    float y;
    asm("ex2.approx.ftz.f32 %0, %1;" : "=f"(y) : "f"(x));
    return y;
}
__device__ __forceinline__ void cpa(uint32_t d, const void* s) {
    asm volatile("cp.async.cg.shared.global [%0], [%1], 16;" :: "r"(d), "l"(s));
}
#define CPCOMMIT() asm volatile("cp.async.commit_group;")
#define CPWAIT1() asm volatile("cp.async.wait_group 1;")
#define CPWAIT0() asm volatile("cp.async.wait_group 0;")

#define LDSM4(R, A) asm volatile( \
    "ldmatrix.sync.aligned.m8n8.x4.shared.b16 {%0,%1,%2,%3},[%4];" \
    : "=r"((R)[0]), "=r"((R)[1]), "=r"((R)[2]), "=r"((R)[3]) : "r"(A))
#define LDSM4T(R, A) asm volatile( \
    "ldmatrix.sync.aligned.m8n8.x4.trans.shared.b16 {%0,%1,%2,%3},[%4];" \
    : "=r"((R)[0]), "=r"((R)[1]), "=r"((R)[2]), "=r"((R)[3]) : "r"(A))
#define MMAH(D, A, B0, B1) asm volatile( \
    "mma.sync.aligned.m16n8k16.row.col.f32.f16.f16.f32 " \
    "{%0,%1,%2,%3},{%4,%5,%6,%7},{%8,%9},{%0,%1,%2,%3};" \
    : "+f"((D)[0]), "+f"((D)[1]), "+f"((D)[2]), "+f"((D)[3]) \
    : "r"((A)[0]), "r"((A)[1]), "r"((A)[2]), "r"((A)[3]), "r"(B0), "r"(B1))

// ---------------------------------------------------------------------------
// Kernel 0: split x into per-head fp16 hi/lo, layout [bh][t][64]
// ---------------------------------------------------------------------------
__global__ void __launch_bounds__(256) splitX(const float* __restrict__ x) {
    int fi = blockIdx.x * 256 + threadIdx.x;
    size_t e = (size_t)fi * 4;
    int b = (int)(e / ((size_t)TT * MM));
    size_t rem = e % ((size_t)TT * MM);
    int t = (int)(rem / MM);
    int col = (int)(rem % MM);
    int h = col >> 6, c = col & 63;
    float4 v = *(const float4*)(x + e);
    float hx = hfh(v.x), hy = hfh(v.y), hz = hfh(v.z), hw = hfh(v.w);
    size_t di = (((size_t)(b * 16 + h) * TT + t) * 64 + c);
    *(uint32_t*)((char*)g_xh + di * 2) = pkh(hx, hy);
    *(uint32_t*)((char*)g_xh + di * 2 + 4) = pkh(hz, hw);
    *(uint32_t*)((char*)g_xl + di * 2) = pkh(v.x - hx, v.y - hy);
    *(uint32_t*)((char*)g_xl + di * 2 + 4) = pkh(v.z - hz, v.w - hw);
}

// ---------------------------------------------------------------------------
// Kernel 1a: partial A; grid (16 h, 8 kseg)
// ---------------------------------------------------------------------------
__global__ void __launch_bounds__(256) computeApart(const float* __restrict__ Wq,
                                                    const float* __restrict__ Wk) {
    const int h = blockIdx.x, ks = blockIdx.y, tid = threadIdx.x;
    const int tx = tid & 15, ty = tid >> 4;
    __shared__ float wqs[64 * 65];
    __shared__ float wks[64 * 65];
    float acc[4][4];
#pragma unroll
    for (int i = 0; i < 4; i++)
#pragma unroll
        for (int j = 0; j < 4; j++) acc[i][j] = 0.f;
    const float* wqh = Wq + (size_t)h * DD * MM;
    const float* wkh = Wk + (size_t)h * DD * MM;
    for (int m0 = ks * 128; m0 < ks * 128 + 128; m0 += 64) {
        __syncthreads();
#pragma unroll
        for (int c = 0; c < 4; c++) {
            int fi = tid + c * 256, i = fi >> 4, q = fi & 15;
            float4 a = *(const float4*)(wqh + i * MM + m0 + q * 4);
            wqs[i * 65 + q * 4 + 0] = a.x; wqs[i * 65 + q * 4 + 1] = a.y;
            wqs[i * 65 + q * 4 + 2] = a.z; wqs[i * 65 + q * 4 + 3] = a.w;
            float4 b = *(const float4*)(wkh + i * MM + m0 + q * 4);
            wks[i * 65 + q * 4 + 0] = b.x; wks[i * 65 + q * 4 + 1] = b.y;
            wks[i * 65 + q * 4 + 2] = b.z; wks[i * 65 + q * 4 + 3] = b.w;
        }
        __syncthreads();
        for (int m = 0; m < 64; m++) {
            float a[4], b[4];
#pragma unroll
            for (int i = 0; i < 4; i++) a[i] = wqs[(ty * 4 + i) * 65 + m];
#pragma unroll
            for (int j = 0; j < 4; j++) b[j] = wks[(tx * 4 + j) * 65 + m];
#pragma unroll
            for (int i = 0; i < 4; i++)
#pragma unroll
                for (int j = 0; j < 4; j++) acc[i][j] += a[i] * b[j];
        }
    }
    float* o = g_Ap + (size_t)ks * (HH * DD * DD) + h * DD * DD;
#pragma unroll
    for (int i = 0; i < 4; i++)
#pragma unroll
        for (int j = 0; j < 4; j++)
            o[(ty * 4 + i) * DD + tx * 4 + j] = acc[i][j];
}

// Kernel 1b: reduce partials, scale, split to fp16 hi/lo
__global__ void __launch_bounds__(256) reduceA() {
    int i = blockIdx.x * 256 + threadIdx.x;
    float s = 0.f;
#pragma unroll
    for (int k = 0; k < 8; k++) s += g_Ap[(size_t)k * (HH * DD * DD) + i];
    s *= (0.125f * 1.4426950408889634f);
    float hv = hfh(s);
    g_Ah[i] = __float2half_rn(s);
    g_Al[i] = __float2half_rn(s - hv);
}

// ---------------------------------------------------------------------------
// Kernel 2: U = Wv_h @ Wo_h — Wv fp16-split x Wo fp16-single, full K=1024,
// 64x64 col-split tiles, direct fp16 output. grid (16 col-tiles, 16 h), 256 thr.
// ---------------------------------------------------------------------------
#define CU_SMEM 29696

__global__ void __launch_bounds__(256, 2) computeUTC(const float* __restrict__ Wv,
                                                     const float* __restrict__ Wo) {
    extern __shared__ __align__(16) char sm[];
    const uint32_t sb = (uint32_t)__cvta_generic_to_shared(sm);
    const uint32_t AH[2] = {0u, 14848u}, AL[2] = {5120u, 19968u};
    const uint32_t BH[2] = {10240u, 25088u};
    const int tid = threadIdx.x, lane = tid & 31, w = tid >> 5;
    const int h = blockIdx.y, col0 = blockIdx.x * 64;
    const int wr = (w & 3) * 16, wc = (w >> 2) * 32;
    const float* wvh = Wv + (size_t)h * DD * MM;
    const float* woh = Wo + (size_t)h * MM * MM;

    // stage chunk 0 (k = 0..31)
#pragma unroll
    for (int c = 0; c < 2; c++) {
        int idx = tid + c * 256;           // 0..511
        int r = idx >> 3, kq = idx & 7;
        float4 v = *(const float4*)(wvh + (size_t)r * MM + kq * 4);
        float hx = hfh(v.x), hy = hfh(v.y), hz = hfh(v.z), hw = hfh(v.w);
        uint32_t o = (uint32_t)(r * 80 + kq * 8);
        *(uint32_t*)(sm + AH[0] + o) = pkh(hx, hy);
        *(uint32_t*)(sm + AH[0] + o + 4) = pkh(hz, hw);
        *(uint32_t*)(sm + AL[0] + o) = pkh(v.x - hx, v.y - hy);
        *(uint32_t*)(sm + AL[0] + o + 4) = pkh(v.z - hz, v.w - hw);
    }
#pragma unroll
    for (int c = 0; c < 2; c++) {
        int idx = tid + c * 256;           // 0..511
        int kk = idx >> 4, q = idx & 15;
        float4 v = *(const float4*)(woh + (size_t)kk * MM + col0 + q * 4);
        uint32_t o = (uint32_t)(kk * 144 + q * 8);
        *(uint32_t*)(sm + BH[0] + o) = pkh(v.x, v.y);
        *(uint32_t*)(sm + BH[0] + o + 4) = pkh(v.z, v.w);
    }
    __syncthreads();

    float acc[4][4];
#pragma unroll
    for (int j = 0; j < 4; j++)
        acc[j][0] = acc[j][1] = acc[j][2] = acc[j][3] = 0.f;

    const uint32_t aro = (uint32_t)((wr + (lane & 15)) * 80 + ((lane >> 4) << 3) * 2);
    const uint32_t bro = (uint32_t)((lane & 15) * 144 + (wc + ((lane >> 4) << 3)) * 2);

    for (int it = 0; it < 32; it++) {
        const int cur = it & 1, nx = cur ^ 1;
        float4 pv[2], po[2];
        if (it < 31) {
            int m0 = (it + 1) * 32;
#pragma unroll
            for (int c = 0; c < 2; c++) {
                int idx = tid + c * 256;
                int r = idx >> 3, kq = idx & 7;
                pv[c] = *(const float4*)(wvh + (size_t)r * MM + m0 + kq * 4);
            }
#pragma unroll
            for (int c = 0; c < 2; c++) {
                int idx = tid + c * 256;
                int kk = idx >> 4, q = idx & 15;
                po[c] = *(const float4*)(woh + (size_t)(m0 + kk) * MM + col0 + q * 4);
            }
        }

#pragma unroll
        for (int kk = 0; kk < 2; kk++) {
            uint32_t ah4[4], al4[4];
            LDSM4(ah4, sb + AH[cur] + aro + kk * 32);
            LDSM4(al4, sb + AL[cur] + aro + kk * 32);
#pragma unroll
            for (int jp = 0; jp < 2; jp++) {
                uint32_t off = (uint32_t)(kk * 2304 + jp * 32);
                uint32_t bh4[4];
                LDSM4T(bh4, sb + BH[cur] + bro + off);
                MMAH(acc[2 * jp], ah4, bh4[0], bh4[1]);
                MMAH(acc[2 * jp], al4, bh4[0], bh4[1]);
                MMAH(acc[2 * jp + 1], ah4, bh4[2], bh4[3]);
                MMAH(acc[2 * jp + 1], al4, bh4[2], bh4[3]);
            }
        }

        if (it < 31) {
#pragma unroll
            for (int c = 0; c < 2; c++) {
                int idx = tid + c * 256;
                int r = idx >> 3, kq = idx & 7;
                float4 v = pv[c];
                float hx = hfh(v.x), hy = hfh(v.y), hz = hfh(v.z), hw = hfh(v.w);
                uint32_t o = (uint32_t)(r * 80 + kq * 8);
                *(uint32_t*)(sm + AH[nx] + o) = pkh(hx, hy);
                *(uint32_t*)(sm + AH[nx] + o + 4) = pkh(hz, hw);
                *(uint32_t*)(sm + AL[nx] + o) = pkh(v.x - hx, v.y - hy);
                *(uint32_t*)(sm + AL[nx] + o + 4) = pkh(v.z - hz, v.w - hw);
            }
#pragma unroll
            for (int c = 0; c < 2; c++) {
                int idx = tid + c * 256;
                int kk = idx >> 4, q = idx & 15;
                float4 v = po[c];
                uint32_t o = (uint32_t)(kk * 144 + q * 8);
                *(uint32_t*)(sm + BH[nx] + o) = pkh(v.x, v.y);
                *(uint32_t*)(sm + BH[nx] + o + 4) = pkh(v.z, v.w);
            }
        }
        __syncthreads();
    }

    // write fp16 U directly
    int r = lane >> 2, cc = (lane & 3) * 2;
    int row = h * 64 + wr + r;
#pragma unroll
    for (int j = 0; j < 4; j++) {
        int gc = col0 + wc + 8 * j + cc;
        *(uint32_t*)((char*)g_Uh + ((size_t)row * MM + gc) * 2) =
            pkh(acc[j][0], acc[j][1]);
        *(uint32_t*)((char*)g_Uh + ((size_t)(row + 8) * MM + gc) * 2) =
            pkh(acc[j][2], acc[j][3]);
    }
}

// ---------------------------------------------------------------------------
// Kernel 4: flash attention — 64-key tiles, K hi-only, 3 CTAs/SM (unchanged)
// ---------------------------------------------------------------------------
#define FL_SMEM 36864

__global__ void __launch_bounds__(128, 3) flashTC() {
    extern __shared__ __align__(16) char sm[];
    const uint32_t sb = (uint32_t)__cvta_generic_to_shared(sm);
    const uint32_t KH0 = 0u, KH1 = 9216u;
    const uint32_t XH = 0u, XL = 9216u, AHs = 18432u, ALs = 27648u;
    const int tid = threadIdx.x, lane = tid & 31, w = tid >> 5;
    const int t0 = blockIdx.x * 64, bh = blockIdx.y;
    const int b = bh >> 4, h = bh & 15;

    const __half* xh = g_xh + (size_t)bh * TT * 64;
    const __half* xl = g_xl + (size_t)bh * TT * 64;

    {
        const __half* Ah = g_Ah + (size_t)h * DD * DD;
        const __half* Al = g_Al + (size_t)h * DD * DD;
#pragma unroll
        for (int c = 0; c < 4; c++) {
            int idx = tid + c * 128;
            int r = idx >> 3, ch = idx & 7;
            cpa(sb + XH + r * 144 + ch * 16, xh + (size_t)(t0 + r) * 64 + ch * 8);
            cpa(sb + XL + r * 144 + ch * 16, xl + (size_t)(t0 + r) * 64 + ch * 8);
            cpa(sb + AHs + r * 144 + ch * 16, Ah + (size_t)r * 64 + ch * 8);
            cpa(sb + ALs + r * 144 + ch * 16, Al + (size_t)r * 64 + ch * 8);
        }
        CPCOMMIT();
        CPWAIT0();
        __syncthreads();
    }

    uint32_t qh[4][4], ql[4][4];
    {
        float QS[8][4];
#pragma unroll
        for (int j = 0; j < 8; j++) { QS[j][0] = QS[j][1] = QS[j][2] = QS[j][3] = 0.f; }
        uint32_t xro = (uint32_t)((16 * w + (lane & 15)) * 144 + ((lane >> 4) << 3) * 2);
        uint32_t aro = (uint32_t)((lane & 15) * 144 + ((lane >> 4) << 3) * 2);
#pragma unroll
        for (int kk = 0; kk < 4; kk++) {
            uint32_t xh4[4], xl4[4];
            LDSM4(xh4, sb + XH + xro + kk * 32);
            LDSM4(xl4, sb + XL + xro + kk * 32);
#pragma unroll
            for (int jp = 0; jp < 4; jp++) {
                uint32_t off = (uint32_t)(kk * 2304 + jp * 32);
                uint32_t bh4[4], bl4[4];
                LDSM4T(bh4, sb + AHs + aro + off);
                LDSM4T(bl4, sb + ALs + aro + off);
                MMAH(QS[2 * jp], xh4, bh4[0], bh4[1]);
                MMAH(QS[2 * jp], xh4, bl4[0], bl4[1]);
                MMAH(QS[2 * jp], xl4, bh4[0], bh4[1]);
                MMAH(QS[2 * jp + 1], xh4, bh4[2], bh4[3]);
                MMAH(QS[2 * jp + 1], xh4, bl4[2], bl4[3]);
                MMAH(QS[2 * jp + 1], xl4, bh4[2], bh4[3]);
            }
        }
#pragma unroll
        for (int j = 0; j < 8; j++) {
            float q0 = QS[j][0], q1 = QS[j][1], q2 = QS[j][2], q3 = QS[j][3];
            float h0 = hfh(q0), h1 = hfh(q1), h2 = hfh(q2), h3 = hfh(q3);
            int kkq = j >> 1, ps = (j & 1) << 1;
            qh[kkq][ps] = pkh(h0, h1);
            qh[kkq][ps + 1] = pkh(h2, h3);
            ql[kkq][ps] = pkh(q0 - h0, q1 - h1);
            ql[kkq][ps + 1] = pkh(q2 - h2, q3 - h3);
        }
    }
    __syncthreads();

#pragma unroll
    for (int c = 0; c < 4; c++) {
        int idx = tid + c * 128;
        int r = idx >> 3, ch = idx & 7;
        cpa(sb + KH0 + r * 144 + ch * 16, xh + (size_t)r * 64 + ch * 8);
    }
    CPCOMMIT();

    float acc[8][4];
    float mrow0 = -INFINITY, mrow1 = -INFINITY, lrow0 = 0.f, lrow1 = 0.f;
#pragma unroll
    for (int j = 0; j < 8; j++) { acc[j][0] = acc[j][1] = acc[j][2] = acc[j][3] = 0.f; }

    const uint32_t rbase1 = sb + (uint32_t)(((lane & 7) + ((lane >> 4) << 3)) * 144 +
                                            (((lane >> 3) & 1) << 3) * 2);
    const uint32_t rbase2 = sb + (uint32_t)((lane & 15) * 144 + ((lane >> 4) << 3) * 2);

    for (int it = 0; it < 32; it++) {
        const uint32_t curH = (it & 1) ? KH1 : KH0;
        const uint32_t nxtH = (it & 1) ? KH0 : KH1;

        __syncthreads();
        if (it < 31) {
            int s0 = (it + 1) * 64;
#pragma unroll
            for (int c = 0; c < 4; c++) {
                int idx = tid + c * 128;
                int r = idx >> 3, ch = idx & 7;
                cpa(sb + nxtH + r * 144 + ch * 16, xh + (size_t)(s0 + r) * 64 + ch * 8);
            }
            CPCOMMIT();
            CPWAIT1();
        } else {
            CPWAIT0();
        }
        __syncthreads();

        float S[8][4];
#pragma unroll
        for (int j = 0; j < 8; j++) { S[j][0] = S[j][1] = S[j][2] = S[j][3] = 0.f; }
#pragma unroll
        for (int jp = 0; jp < 4; jp++) {
#pragma unroll
            for (int kk = 0; kk < 4; kk++) {
                uint32_t off = (uint32_t)(jp * 2304 + kk * 32);
                uint32_t bh4[4];
                LDSM4(bh4, rbase1 + curH + off);
                MMAH(S[2 * jp], qh[kk], bh4[0], bh4[1]);
                MMAH(S[2 * jp], ql[kk], bh4[0], bh4[1]);
                MMAH(S[2 * jp + 1], qh[kk], bh4[2], bh4[3]);
                MMAH(S[2 * jp + 1], ql[kk], bh4[2], bh4[3]);
            }
        }

        float mx0 = -INFINITY, mx1 = -INFINITY;
#pragma unroll
        for (int j = 0; j < 8; j++) {
            mx0 = fmaxf(mx0, fmaxf(S[j][0], S[j][1]));
            mx1 = fmaxf(mx1, fmaxf(S[j][2], S[j][3]));
        }
        mx0 = fmaxf(mx0, __shfl_xor_sync(0xffffffffu, mx0, 1));
        mx0 = fmaxf(mx0, __shfl_xor_sync(0xffffffffu, mx0, 2));
        mx1 = fmaxf(mx1, __shfl_xor_sync(0xffffffffu, mx1, 1));
        mx1 = fmaxf(mx1, __shfl_xor_sync(0xffffffffu, mx1, 2));
        float mn0 = fmaxf(mrow0, mx0), mn1 = fmaxf(mrow1, mx1);
        float sc0 = ex2f(mrow0 - mn0), sc1 = ex2f(mrow1 - mn1);
        mrow0 = mn0; mrow1 = mn1;

        uint32_t php[4][4];
        float rs0 = 0.f, rs1 = 0.f;
#pragma unroll
        for (int j = 0; j < 8; j++) {
            float p0 = ex2f(S[j][0] - mn0), p1 = ex2f(S[j][1] - mn0);
            float p2 = ex2f(S[j][2] - mn1), p3 = ex2f(S[j][3] - mn1);
            rs0 += p0 + p1; rs1 += p2 + p3;
            int ss = j >> 1, ps = (j & 1) << 1;
            php[ss][ps] = pkh(p0, p1);
            php[ss][ps + 1] = pkh(p2, p3);
        }
        rs0 += __shfl_xor_sync(0xffffffffu, rs0, 1);
        rs0 += __shfl_xor_sync(0xffffffffu, rs0, 2);
        rs1 += __shfl_xor_sync(0xffffffffu, rs1, 1);
        rs1 += __shfl_xor_sync(0xffffffffu, rs1, 2);
        lrow0 = lrow0 * sc0 + rs0;
        lrow1 = lrow1 * sc1 + rs1;
#pragma unroll
        for (int j = 0; j < 8; j++) {
            acc[j][0] *= sc0; acc[j][1] *= sc0; acc[j][2] *= sc1; acc[j][3] *= sc1;
        }

#pragma unroll
        for (int ss = 0; ss < 4; ss++) {
#pragma unroll
            for (int jp = 0; jp < 4; jp++) {
                uint32_t off = (uint32_t)(ss * 2304 + jp * 32);
                uint32_t vh4[4];
                LDSM4T(vh4, rbase2 + curH + off);
                MMAH(acc[2 * jp], php[ss], vh4[0], vh4[1]);
                MMAH(acc[2 * jp + 1], php[ss], vh4[2], vh4[3]);
            }
        }
    }

    float inv0 = 1.f / lrow0, inv1 = 1.f / lrow1;
    int r0 = lane >> 2, c0 = (lane & 3) * 2;
    size_t rowA = ((size_t)b * TT + t0 + 16 * w + r0) * MM + h * 64;
    size_t rowB = rowA + 8 * MM;
#pragma unroll
    for (int j = 0; j < 8; j++) {
        float o0 = acc[j][0] * inv0, o1 = acc[j][1] * inv0;
        float o2 = acc[j][2] * inv1, o3 = acc[j][3] * inv1;
        float h0 = hfh(o0), h1 = hfh(o1), h2 = hfh(o2), h3 = hfh(o3);
        size_t ia = rowA + 8 * j + c0, ib = rowB + 8 * j + c0;
        *(uint32_t*)((char*)g_zh + ia * 2) = pkh(h0, h1);
        *(uint32_t*)((char*)g_zl + ia * 2) = pkh(o0 - h0, o1 - h1);
        *(uint32_t*)((char*)g_zh + ib * 2) = pkh(h2, h3);
        *(uint32_t*)((char*)g_zl + ib * 2) = pkh(o2 - h2, o3 - h3);
    }
}

// ---------------------------------------------------------------------------
// Kernel 5: out = z @ U + bo — 256 threads, tile 128x128, k-chunk 64, 2 CTA/SM
// ---------------------------------------------------------------------------
#define GO_SMEM 108544

__global__ void __launch_bounds__(256, 2) gemmOutTC(const float* __restrict__ bo,
                                                    float* __restrict__ out) {
    extern __shared__ __align__(16) char sm[];
    const uint32_t sb = (uint32_t)__cvta_generic_to_shared(sm);
    const uint32_t ZH[2] = {0u, 54272u}, ZL[2] = {18432u, 72704u};
    const uint32_t UH[2] = {36864u, 91136u};
    const int tid = threadIdx.x, lane = tid & 31, w = tid >> 5;
    const int col0 = blockIdx.x * 128, row0 = blockIdx.y * 128;
    const int wr = (w & 3) * 32, wc = (w >> 2) * 64;

#pragma unroll
    for (int c = 0; c < 4; c++) {
        int idx = tid + c * 256;
        int r = idx >> 3, ch = idx & 7;
        cpa(sb + ZH[0] + r * 144 + ch * 16, g_zh + (size_t)(row0 + r) * MM + ch * 8);
        cpa(sb + ZL[0] + r * 144 + ch * 16, g_zl + (size_t)(row0 + r) * MM + ch * 8);
        int kk = idx >> 4, q = idx & 15;
        cpa(sb + UH[0] + kk * 272 + q * 16, g_Uh + (size_t)kk * MM + col0 + q * 8);
    }
    CPCOMMIT();

    float acc[2][8][4];
#pragma unroll
    for (int rb = 0; rb < 2; rb++)
#pragma unroll
        for (int j = 0; j < 8; j++)
            acc[rb][j][0] = acc[rb][j][1] = acc[rb][j][2] = acc[rb][j][3] = 0.f;

    const uint32_t aro = (uint32_t)((wr + (lane & 15)) * 144 + ((lane >> 4) << 3) * 2);
    const uint32_t bro = (uint32_t)((lane & 15) * 272 + (wc + ((lane >> 4) << 3)) * 2);

    for (int it = 0; it < 16; it++) {
        const int cur = it & 1, nx = cur ^ 1;
        __syncthreads();
        if (it < 15) {
            int k0 = (it + 1) * 64;
#pragma unroll
            for (int c = 0; c < 4; c++) {
                int idx = tid + c * 256;
                int r = idx >> 3, ch = idx & 7;
                cpa(sb + ZH[nx] + r * 144 + ch * 16,
                    g_zh + (size_t)(row0 + r) * MM + k0 + ch * 8);
                cpa(sb + ZL[nx] + r * 144 + ch * 16,
                    g_zl + (size_t)(row0 + r) * MM + k0 + ch * 8);
                int kk = idx >> 4, q = idx & 15;
                cpa(sb + UH[nx] + kk * 272 + q * 16,
                    g_Uh + (size_t)(k0 + kk) * MM + col0 + q * 8);
            }
            CPCOMMIT();
            CPWAIT1();
        } else {
            CPWAIT0();
        }
        __syncthreads();

#pragma unroll
        for (int kk = 0; kk < 4; kk++) {
            uint32_t ah0[4], al0[4], ah1[4], al1[4];
            LDSM4(ah0, sb + ZH[cur] + aro + kk * 32);
            LDSM4(al0, sb + ZL[cur] + aro + kk * 32);
            LDSM4(ah1, sb + ZH[cur] + aro + 2304 + kk * 32);
            LDSM4(al1, sb + ZL[cur] + aro + 2304 + kk * 32);
#pragma unroll
            for (int jp = 0; jp < 4; jp++) {
                uint32_t off = (uint32_t)(kk * 4352 + jp * 32);
                uint32_t bh4[4];
                LDSM4T(bh4, sb + UH[cur] + bro + off);
                MMAH(acc[0][2 * jp], ah0, bh4[0], bh4[1]);
                MMAH(acc[0][2 * jp], al0, bh4[0], bh4[1]);
                MMAH(acc[0][2 * jp + 1], ah0, bh4[2], bh4[3]);
                MMAH(acc[0][2 * jp + 1], al0, bh4[2], bh4[3]);
                MMAH(acc[1][2 * jp], ah1, bh4[0], bh4[1]);
                MMAH(acc[1][2 * jp], al1, bh4[0], bh4[1]);
                MMAH(acc[1][2 * jp + 1], ah1, bh4[2], bh4[3]);
                MMAH(acc[1][2 * jp + 1], al1, bh4[2], bh4[3]);
            }
        }
    }

    int r = lane >> 2, cc = (lane & 3) * 2;
#pragma unroll
    for (int rb = 0; rb < 2; rb++) {
        int gr = row0 + wr + rb * 16 + r;
#pragma unroll
        for (int j = 0; j < 8; j++) {
            int gc = col0 + wc + 8 * j + cc;
            float b0v = bo[gc], b1v = bo[gc + 1];
            *(float2*)(out + (size_t)gr * MM + gc) =
                make_float2(acc[rb][j][0] + b0v, acc[rb][j][1] + b1v);
            *(float2*)(out + (size_t)(gr + 8) * MM + gc) =
                make_float2(acc[rb][j][2] + b0v, acc[rb][j][3] + b1v);
        }
    }
}

// ---------------------------------------------------------------------------
extern "C" void kernel_launch(void* const* d_in, const int* in_sizes, int n_in,
                              void* d_out, int out_size) {
    const float* x  = (const float*)d_in[0];
    const float* Wq = (const float*)d_in[1];
    const float* Wk = (const float*)d_in[2];
    const float* Wv = (const float*)d_in[3];
    const float* Wo = (const float*)d_in[4];
    const float* bo = (const float*)d_in[5];
    float* out = (float*)d_out;

    cudaFuncSetAttribute(flashTC, cudaFuncAttributeMaxDynamicSharedMemorySize, FL_SMEM);
    cudaFuncSetAttribute(gemmOutTC, cudaFuncAttributeMaxDynamicSharedMemorySize, GO_SMEM);
    cudaFuncSetAttribute(computeUTC, cudaFuncAttributeMaxDynamicSharedMemorySize, CU_SMEM);

    splitX<<<4096, 256>>>(x);
    computeApart<<<dim3(16, 8), 256>>>(Wq, Wk);
    reduceA<<<256, 256>>>();
    computeUTC<<<dim3(16, 16), 256, CU_SMEM>>>(Wv, Wo);
    flashTC<<<dim3(TT / 64, BB * HH), 128, FL_SMEM>>>();
    gemmOutTC<<<dim3(MM / 128, (BB * TT) / 128), 256, GO_SMEM>>>(bo, out);
}

// round 16
// speedup vs baseline: 1.1135x; 1.1036x over previous
#include <cuda_runtime.h>
#include <cuda_fp16.h>
#include <math.h>
#include <stdint.h>

#define BB 2
#define TT 2048
#define HH 16
#define DD 64
#define MM 1024

// Persistent scratch (device globals)
__device__ float g_Ap[8 * HH * DD * DD];        // k-split partials for A
__device__ __half g_Ah[HH * DD * DD];           // A split hi  [h][d][d']
__device__ __half g_Al[HH * DD * DD];           // A split lo
__device__ __half g_xh[BB * HH * TT * DD];      // x per-head, fp16 hi  [bh][t][64]
__device__ __half g_xl[BB * HH * TT * DD];      // x per-head, fp16 lo
__device__ __half g_zh[BB * TT * MM];           // attn out, fp16 hi    [b][t][1024]
__device__ __half g_zl[BB * TT * MM];
__device__ __half g_Uh[MM * MM];                // U = Wv@Wo, fp16 (single)

__device__ __forceinline__ uint32_t pkh(float a, float b) {
    __half2 t = __floats2half2_rn(a, b);
    return *reinterpret_cast<uint32_t*>(&t);
}
__device__ __forceinline__ float hfh(float x) {
    return __half2float(__float2half_rn(x));
}
__device__ __forceinline__ float ex2f(float x) {
    float y;
    asm("ex2.approx.ftz.f32 %0, %1;" : "=f"(y) : "f"(x));
    return y;
}
__device__ __forceinline__ void cpa(uint32_t d, const void* s) {
    asm volatile("cp.async.cg.shared.global [%0], [%1], 16;" :: "r"(d), "l"(s));
}
#define CPCOMMIT() asm volatile("cp.async.commit_group;")
#define CPWAIT1() asm volatile("cp.async.wait_group 1;")
#define CPWAIT0() asm volatile("cp.async.wait_group 0;")

#define LDSM4(R, A) asm volatile( \
    "ldmatrix.sync.aligned.m8n8.x4.shared.b16 {%0,%1,%2,%3},[%4];" \
    : "=r"((R)[0]), "=r"((R)[1]), "=r"((R)[2]), "=r"((R)[3]) : "r"(A))
#define LDSM4T(R, A) asm volatile( \
    "ldmatrix.sync.aligned.m8n8.x4.trans.shared.b16 {%0,%1,%2,%3},[%4];" \
    : "=r"((R)[0]), "=r"((R)[1]), "=r"((R)[2]), "=r"((R)[3]) : "r"(A))
#define MMAH(D, A, B0, B1) asm volatile( \
    "mma.sync.aligned.m16n8k16.row.col.f32.f16.f16.f32 " \
    "{%0,%1,%2,%3},{%4,%5,%6,%7},{%8,%9},{%0,%1,%2,%3};" \
    : "+f"((D)[0]), "+f"((D)[1]), "+f"((D)[2]), "+f"((D)[3]) \
    : "r"((A)[0]), "r"((A)[1]), "r"((A)[2]), "r"((A)[3]), "r"(B0), "r"(B1))

// ---------------------------------------------------------------------------
// Kernel 0: split x into per-head fp16 hi/lo, layout [bh][t][64]
// ---------------------------------------------------------------------------
__global__ void __launch_bounds__(256) splitX(const float* __restrict__ x) {
    int fi = blockIdx.x * 256 + threadIdx.x;
    size_t e = (size_t)fi * 4;
    int b = (int)(e / ((size_t)TT * MM));
    size_t rem = e % ((size_t)TT * MM);
    int t = (int)(rem / MM);
    int col = (int)(rem % MM);
    int h = col >> 6, c = col & 63;
    float4 v = *(const float4*)(x + e);
    float hx = hfh(v.x), hy = hfh(v.y), hz = hfh(v.z), hw = hfh(v.w);
    size_t di = (((size_t)(b * 16 + h) * TT + t) * 64 + c);
    *(uint32_t*)((char*)g_xh + di * 2) = pkh(hx, hy);
    *(uint32_t*)((char*)g_xh + di * 2 + 4) = pkh(hz, hw);
    *(uint32_t*)((char*)g_xl + di * 2) = pkh(v.x - hx, v.y - hy);
    *(uint32_t*)((char*)g_xl + di * 2 + 4) = pkh(v.z - hz, v.w - hw);
}

// ---------------------------------------------------------------------------
// Kernel 1a: partial A; grid (16 h, 8 kseg)
// ---------------------------------------------------------------------------
__global__ void __launch_bounds__(256) computeApart(const float* __restrict__ Wq,
                                                    const float* __restrict__ Wk) {
    const int h = blockIdx.x, ks = blockIdx.y, tid = threadIdx.x;
    const int tx = tid & 15, ty = tid >> 4;
    __shared__ float wqs[64 * 65];
    __shared__ float wks[64 * 65];
    float acc[4][4];
#pragma unroll
    for (int i = 0; i < 4; i++)
#pragma unroll
        for (int j = 0; j < 4; j++) acc[i][j] = 0.f;
    const float* wqh = Wq + (size_t)h * DD * MM;
    const float* wkh = Wk + (size_t)h * DD * MM;
    for (int m0 = ks * 128; m0 < ks * 128 + 128; m0 += 64) {
        __syncthreads();
#pragma unroll
        for (int c = 0; c < 4; c++) {
            int fi = tid + c * 256, i = fi >> 4, q = fi & 15;
            float4 a = *(const float4*)(wqh + i * MM + m0 + q * 4);
            wqs[i * 65 + q * 4 + 0] = a.x; wqs[i * 65 + q * 4 + 1] = a.y;
            wqs[i * 65 + q * 4 + 2] = a.z; wqs[i * 65 + q * 4 + 3] = a.w;
            float4 b = *(const float4*)(wkh + i * MM + m0 + q * 4);
            wks[i * 65 + q * 4 + 0] = b.x; wks[i * 65 + q * 4 + 1] = b.y;
            wks[i * 65 + q * 4 + 2] = b.z; wks[i * 65 + q * 4 + 3] = b.w;
        }
        __syncthreads();
        for (int m = 0; m < 64; m++) {
            float a[4], b[4];
#pragma unroll
            for (int i = 0; i < 4; i++) a[i] = wqs[(ty * 4 + i) * 65 + m];
#pragma unroll
            for (int j = 0; j < 4; j++) b[j] = wks[(tx * 4 + j) * 65 + m];
#pragma unroll
            for (int i = 0; i < 4; i++)
#pragma unroll
                for (int j = 0; j < 4; j++) acc[i][j] += a[i] * b[j];
        }
    }
    float* o = g_Ap + (size_t)ks * (HH * DD * DD) + h * DD * DD;
#pragma unroll
    for (int i = 0; i < 4; i++)
#pragma unroll
        for (int j = 0; j < 4; j++)
            o[(ty * 4 + i) * DD + tx * 4 + j] = acc[i][j];
}

// Kernel 1b: reduce partials, scale, split to fp16 hi/lo
__global__ void __launch_bounds__(256) reduceA() {
    int i = blockIdx.x * 256 + threadIdx.x;
    float s = 0.f;
#pragma unroll
    for (int k = 0; k < 8; k++) s += g_Ap[(size_t)k * (HH * DD * DD) + i];
    s *= (0.125f * 1.4426950408889634f);
    float hv = hfh(s);
    g_Ah[i] = __float2half_rn(s);
    g_Al[i] = __float2half_rn(s - hv);
}

// ---------------------------------------------------------------------------
// Kernel 2: U = Wv_h @ Wo_h — Wv fp16-split x Wo fp16-single, full K=1024,
// 64x64 col-split tiles, direct fp16 output. grid (16 col-tiles, 16 h), 256 thr.
// ---------------------------------------------------------------------------
#define CU_SMEM 29696

__global__ void __launch_bounds__(256, 2) computeUTC(const float* __restrict__ Wv,
                                                     const float* __restrict__ Wo) {
    extern __shared__ __align__(16) char sm[];
    const uint32_t sb = (uint32_t)__cvta_generic_to_shared(sm);
    const uint32_t AH[2] = {0u, 14848u}, AL[2] = {5120u, 19968u};
    const uint32_t BH[2] = {10240u, 25088u};
    const int tid = threadIdx.x, lane = tid & 31, w = tid >> 5;
    const int h = blockIdx.y, col0 = blockIdx.x * 64;
    const int wr = (w & 3) * 16, wc = (w >> 2) * 32;
    const float* wvh = Wv + (size_t)h * DD * MM;
    const float* woh = Wo + (size_t)h * MM * MM;

#pragma unroll
    for (int c = 0; c < 2; c++) {
        int idx = tid + c * 256;
        int r = idx >> 3, kq = idx & 7;
        float4 v = *(const float4*)(wvh + (size_t)r * MM + kq * 4);
        float hx = hfh(v.x), hy = hfh(v.y), hz = hfh(v.z), hw = hfh(v.w);
        uint32_t o = (uint32_t)(r * 80 + kq * 8);
        *(uint32_t*)(sm + AH[0] + o) = pkh(hx, hy);
        *(uint32_t*)(sm + AH[0] + o + 4) = pkh(hz, hw);
        *(uint32_t*)(sm + AL[0] + o) = pkh(v.x - hx, v.y - hy);
        *(uint32_t*)(sm + AL[0] + o + 4) = pkh(v.z - hz, v.w - hw);
    }
#pragma unroll
    for (int c = 0; c < 2; c++) {
        int idx = tid + c * 256;
        int kk = idx >> 4, q = idx & 15;
        float4 v = *(const float4*)(woh + (size_t)kk * MM + col0 + q * 4);
        uint32_t o = (uint32_t)(kk * 144 + q * 8);
        *(uint32_t*)(sm + BH[0] + o) = pkh(v.x, v.y);
        *(uint32_t*)(sm + BH[0] + o + 4) = pkh(v.z, v.w);
    }
    __syncthreads();

    float acc[4][4];
#pragma unroll
    for (int j = 0; j < 4; j++)
        acc[j][0] = acc[j][1] = acc[j][2] = acc[j][3] = 0.f;

    const uint32_t aro = (uint32_t)((wr + (lane & 15)) * 80 + ((lane >> 4) << 3) * 2);
    const uint32_t bro = (uint32_t)((lane & 15) * 144 + (wc + ((lane >> 4) << 3)) * 2);

    for (int it = 0; it < 32; it++) {
        const int cur = it & 1, nx = cur ^ 1;
        float4 pv[2], po[2];
        if (it < 31) {
            int m0 = (it + 1) * 32;
#pragma unroll
            for (int c = 0; c < 2; c++) {
                int idx = tid + c * 256;
                int r = idx >> 3, kq = idx & 7;
                pv[c] = *(const float4*)(wvh + (size_t)r * MM + m0 + kq * 4);
            }
#pragma unroll
            for (int c = 0; c < 2; c++) {
                int idx = tid + c * 256;
                int kk = idx >> 4, q = idx & 15;
                po[c] = *(const float4*)(woh + (size_t)(m0 + kk) * MM + col0 + q * 4);
            }
        }

#pragma unroll
        for (int kk = 0; kk < 2; kk++) {
            uint32_t ah4[4], al4[4];
            LDSM4(ah4, sb + AH[cur] + aro + kk * 32);
            LDSM4(al4, sb + AL[cur] + aro + kk * 32);
#pragma unroll
            for (int jp = 0; jp < 2; jp++) {
                uint32_t off = (uint32_t)(kk * 2304 + jp * 32);
                uint32_t bh4[4];
                LDSM4T(bh4, sb + BH[cur] + bro + off);
                MMAH(acc[2 * jp], ah4, bh4[0], bh4[1]);
                MMAH(acc[2 * jp], al4, bh4[0], bh4[1]);
                MMAH(acc[2 * jp + 1], ah4, bh4[2], bh4[3]);
                MMAH(acc[2 * jp + 1], al4, bh4[2], bh4[3]);
            }
        }

        if (it < 31) {
#pragma unroll
            for (int c = 0; c < 2; c++) {
                int idx = tid + c * 256;
                int r = idx >> 3, kq = idx & 7;
                float4 v = pv[c];
                float hx = hfh(v.x), hy = hfh(v.y), hz = hfh(v.z), hw = hfh(v.w);
                uint32_t o = (uint32_t)(r * 80 + kq * 8);
                *(uint32_t*)(sm + AH[nx] + o) = pkh(hx, hy);
                *(uint32_t*)(sm + AH[nx] + o + 4) = pkh(hz, hw);
                *(uint32_t*)(sm + AL[nx] + o) = pkh(v.x - hx, v.y - hy);
                *(uint32_t*)(sm + AL[nx] + o + 4) = pkh(v.z - hz, v.w - hw);
            }
#pragma unroll
            for (int c = 0; c < 2; c++) {
                int idx = tid + c * 256;
                int kk = idx >> 4, q = idx & 15;
                float4 v = po[c];
                uint32_t o = (uint32_t)(kk * 144 + q * 8);
                *(uint32_t*)(sm + BH[nx] + o) = pkh(v.x, v.y);
                *(uint32_t*)(sm + BH[nx] + o + 4) = pkh(v.z, v.w);
            }
        }
        __syncthreads();
    }

    int r = lane >> 2, cc = (lane & 3) * 2;
    int row = h * 64 + wr + r;
#pragma unroll
    for (int j = 0; j < 4; j++) {
        int gc = col0 + wc + 8 * j + cc;
        *(uint32_t*)((char*)g_Uh + ((size_t)row * MM + gc) * 2) =
            pkh(acc[j][0], acc[j][1]);
        *(uint32_t*)((char*)g_Uh + ((size_t)(row + 8) * MM + gc) * 2) =
            pkh(acc[j][2], acc[j][3]);
    }
}

// ---------------------------------------------------------------------------
// Kernel 4: flash attention — 64-key tiles, K hi-only, 3 CTAs/SM
// ---------------------------------------------------------------------------
#define FL_SMEM 36864

__global__ void __launch_bounds__(128, 3) flashTC() {
    extern __shared__ __align__(16) char sm[];
    const uint32_t sb = (uint32_t)__cvta_generic_to_shared(sm);
    const uint32_t KH0 = 0u, KH1 = 9216u;
    const uint32_t XH = 0u, XL = 9216u, AHs = 18432u, ALs = 27648u;
    const int tid = threadIdx.x, lane = tid & 31, w = tid >> 5;
    const int t0 = blockIdx.x * 64, bh = blockIdx.y;
    const int b = bh >> 4, h = bh & 15;

    const __half* xh = g_xh + (size_t)bh * TT * 64;
    const __half* xl = g_xl + (size_t)bh * TT * 64;

    {
        const __half* Ah = g_Ah + (size_t)h * DD * DD;
        const __half* Al = g_Al + (size_t)h * DD * DD;
#pragma unroll
        for (int c = 0; c < 4; c++) {
            int idx = tid + c * 128;
            int r = idx >> 3, ch = idx & 7;
            cpa(sb + XH + r * 144 + ch * 16, xh + (size_t)(t0 + r) * 64 + ch * 8);
            cpa(sb + XL + r * 144 + ch * 16, xl + (size_t)(t0 + r) * 64 + ch * 8);
            cpa(sb + AHs + r * 144 + ch * 16, Ah + (size_t)r * 64 + ch * 8);
            cpa(sb + ALs + r * 144 + ch * 16, Al + (size_t)r * 64 + ch * 8);
        }
        CPCOMMIT();
        CPWAIT0();
        __syncthreads();
    }

    uint32_t qh[4][4], ql[4][4];
    {
        float QS[8][4];
#pragma unroll
        for (int j = 0; j < 8; j++) { QS[j][0] = QS[j][1] = QS[j][2] = QS[j][3] = 0.f; }
        uint32_t xro = (uint32_t)((16 * w + (lane & 15)) * 144 + ((lane >> 4) << 3) * 2);
        uint32_t aro = (uint32_t)((lane & 15) * 144 + ((lane >> 4) << 3) * 2);
#pragma unroll
        for (int kk = 0; kk < 4; kk++) {
            uint32_t xh4[4], xl4[4];
            LDSM4(xh4, sb + XH + xro + kk * 32);
            LDSM4(xl4, sb + XL + xro + kk * 32);
#pragma unroll
            for (int jp = 0; jp < 4; jp++) {
                uint32_t off = (uint32_t)(kk * 2304 + jp * 32);
                uint32_t bh4[4], bl4[4];
                LDSM4T(bh4, sb + AHs + aro + off);
                LDSM4T(bl4, sb + ALs + aro + off);
                MMAH(QS[2 * jp], xh4, bh4[0], bh4[1]);
                MMAH(QS[2 * jp], xh4, bl4[0], bl4[1]);
                MMAH(QS[2 * jp], xl4, bh4[0], bh4[1]);
                MMAH(QS[2 * jp + 1], xh4, bh4[2], bh4[3]);
                MMAH(QS[2 * jp + 1], xh4, bl4[2], bl4[3]);
                MMAH(QS[2 * jp + 1], xl4, bh4[2], bh4[3]);
            }
        }
#pragma unroll
        for (int j = 0; j < 8; j++) {
            float q0 = QS[j][0], q1 = QS[j][1], q2 = QS[j][2], q3 = QS[j][3];
            float h0 = hfh(q0), h1 = hfh(q1), h2 = hfh(q2), h3 = hfh(q3);
            int kkq = j >> 1, ps = (j & 1) << 1;
            qh[kkq][ps] = pkh(h0, h1);
            qh[kkq][ps + 1] = pkh(h2, h3);
            ql[kkq][ps] = pkh(q0 - h0, q1 - h1);
            ql[kkq][ps + 1] = pkh(q2 - h2, q3 - h3);
        }
    }
    __syncthreads();

#pragma unroll
    for (int c = 0; c < 4; c++) {
        int idx = tid + c * 128;
        int r = idx >> 3, ch = idx & 7;
        cpa(sb + KH0 + r * 144 + ch * 16, xh + (size_t)r * 64 + ch * 8);
    }
    CPCOMMIT();

    float acc[8][4];
    float mrow0 = -INFINITY, mrow1 = -INFINITY, lrow0 = 0.f, lrow1 = 0.f;
#pragma unroll
    for (int j = 0; j < 8; j++) { acc[j][0] = acc[j][1] = acc[j][2] = acc[j][3] = 0.f; }

    const uint32_t rbase1 = sb + (uint32_t)(((lane & 7) + ((lane >> 4) << 3)) * 144 +
                                            (((lane >> 3) & 1) << 3) * 2);
    const uint32_t rbase2 = sb + (uint32_t)((lane & 15) * 144 + ((lane >> 4) << 3) * 2);

    for (int it = 0; it < 32; it++) {
        const uint32_t curH = (it & 1) ? KH1 : KH0;
        const uint32_t nxtH = (it & 1) ? KH0 : KH1;

        __syncthreads();
        if (it < 31) {
            int s0 = (it + 1) * 64;
#pragma unroll
            for (int c = 0; c < 4; c++) {
                int idx = tid + c * 128;
                int r = idx >> 3, ch = idx & 7;
                cpa(sb + nxtH + r * 144 + ch * 16, xh + (size_t)(s0 + r) * 64 + ch * 8);
            }
            CPCOMMIT();
            CPWAIT1();
        } else {
            CPWAIT0();
        }
        __syncthreads();

        float S[8][4];
#pragma unroll
        for (int j = 0; j < 8; j++) { S[j][0] = S[j][1] = S[j][2] = S[j][3] = 0.f; }
#pragma unroll
        for (int jp = 0; jp < 4; jp++) {
#pragma unroll
            for (int kk = 0; kk < 4; kk++) {
                uint32_t off = (uint32_t)(jp * 2304 + kk * 32);
                uint32_t bh4[4];
                LDSM4(bh4, rbase1 + curH + off);
                MMAH(S[2 * jp], qh[kk], bh4[0], bh4[1]);
                MMAH(S[2 * jp], ql[kk], bh4[0], bh4[1]);
                MMAH(S[2 * jp + 1], qh[kk], bh4[2], bh4[3]);
                MMAH(S[2 * jp + 1], ql[kk], bh4[2], bh4[3]);
            }
        }

        float mx0 = -INFINITY, mx1 = -INFINITY;
#pragma unroll
        for (int j = 0; j < 8; j++) {
            mx0 = fmaxf(mx0, fmaxf(S[j][0], S[j][1]));
            mx1 = fmaxf(mx1, fmaxf(S[j][2], S[j][3]));
        }
        mx0 = fmaxf(mx0, __shfl_xor_sync(0xffffffffu, mx0, 1));
        mx0 = fmaxf(mx0, __shfl_xor_sync(0xffffffffu, mx0, 2));
        mx1 = fmaxf(mx1, __shfl_xor_sync(0xffffffffu, mx1, 1));
        mx1 = fmaxf(mx1, __shfl_xor_sync(0xffffffffu, mx1, 2));
        float mn0 = fmaxf(mrow0, mx0), mn1 = fmaxf(mrow1, mx1);
        float sc0 = ex2f(mrow0 - mn0), sc1 = ex2f(mrow1 - mn1);
        mrow0 = mn0; mrow1 = mn1;

        uint32_t php[4][4];
        float rs0 = 0.f, rs1 = 0.f;
#pragma unroll
        for (int j = 0; j < 8; j++) {
            float p0 = ex2f(S[j][0] - mn0), p1 = ex2f(S[j][1] - mn0);
            float p2 = ex2f(S[j][2] - mn1), p3 = ex2f(S[j][3] - mn1);
            rs0 += p0 + p1; rs1 += p2 + p3;
            int ss = j >> 1, ps = (j & 1) << 1;
            php[ss][ps] = pkh(p0, p1);
            php[ss][ps + 1] = pkh(p2, p3);
        }
        rs0 += __shfl_xor_sync(0xffffffffu, rs0, 1);
        rs0 += __shfl_xor_sync(0xffffffffu, rs0, 2);
        rs1 += __shfl_xor_sync(0xffffffffu, rs1, 1);
        rs1 += __shfl_xor_sync(0xffffffffu, rs1, 2);
        lrow0 = lrow0 * sc0 + rs0;
        lrow1 = lrow1 * sc1 + rs1;
#pragma unroll
        for (int j = 0; j < 8; j++) {
            acc[j][0] *= sc0; acc[j][1] *= sc0; acc[j][2] *= sc1; acc[j][3] *= sc1;
        }

#pragma unroll
        for (int ss = 0; ss < 4; ss++) {
#pragma unroll
            for (int jp = 0; jp < 4; jp++) {
                uint32_t off = (uint32_t)(ss * 2304 + jp * 32);
                uint32_t vh4[4];
                LDSM4T(vh4, rbase2 + curH + off);
                MMAH(acc[2 * jp], php[ss], vh4[0], vh4[1]);
                MMAH(acc[2 * jp + 1], php[ss], vh4[2], vh4[3]);
            }
        }
    }

    float inv0 = 1.f / lrow0, inv1 = 1.f / lrow1;
    int r0 = lane >> 2, c0 = (lane & 3) * 2;
    size_t rowA = ((size_t)b * TT + t0 + 16 * w + r0) * MM + h * 64;
    size_t rowB = rowA + 8 * MM;
#pragma unroll
    for (int j = 0; j < 8; j++) {
        float o0 = acc[j][0] * inv0, o1 = acc[j][1] * inv0;
        float o2 = acc[j][2] * inv1, o3 = acc[j][3] * inv1;
        float h0 = hfh(o0), h1 = hfh(o1), h2 = hfh(o2), h3 = hfh(o3);
        size_t ia = rowA + 8 * j + c0, ib = rowB + 8 * j + c0;
        *(uint32_t*)((char*)g_zh + ia * 2) = pkh(h0, h1);
        *(uint32_t*)((char*)g_zl + ia * 2) = pkh(o0 - h0, o1 - h1);
        *(uint32_t*)((char*)g_zh + ib * 2) = pkh(h2, h3);
        *(uint32_t*)((char*)g_zl + ib * 2) = pkh(o2 - h2, o3 - h3);
    }
}

// ---------------------------------------------------------------------------
// Kernel 5: out = z @ U + bo — 256 threads, tile 128x128, k-chunk 64, 2 CTA/SM
// ---------------------------------------------------------------------------
#define GO_SMEM 108544

__global__ void __launch_bounds__(256, 2) gemmOutTC(const float* __restrict__ bo,
                                                    float* __restrict__ out) {
    extern __shared__ __align__(16) char sm[];
    const uint32_t sb = (uint32_t)__cvta_generic_to_shared(sm);
    const uint32_t ZH[2] = {0u, 54272u}, ZL[2] = {18432u, 72704u};
    const uint32_t UH[2] = {36864u, 91136u};
    const int tid = threadIdx.x, lane = tid & 31, w = tid >> 5;
    const int col0 = blockIdx.x * 128, row0 = blockIdx.y * 128;
    const int wr = (w & 3) * 32, wc = (w >> 2) * 64;

#pragma unroll
    for (int c = 0; c < 4; c++) {
        int idx = tid + c * 256;
        int r = idx >> 3, ch = idx & 7;
        cpa(sb + ZH[0] + r * 144 + ch * 16, g_zh + (size_t)(row0 + r) * MM + ch * 8);
        cpa(sb + ZL[0] + r * 144 + ch * 16, g_zl + (size_t)(row0 + r) * MM + ch * 8);
        int kk = idx >> 4, q = idx & 15;
        cpa(sb + UH[0] + kk * 272 + q * 16, g_Uh + (size_t)kk * MM + col0 + q * 8);
    }
    CPCOMMIT();

    float acc[2][8][4];
#pragma unroll
    for (int rb = 0; rb < 2; rb++)
#pragma unroll
        for (int j = 0; j < 8; j++)
            acc[rb][j][0] = acc[rb][j][1] = acc[rb][j][2] = acc[rb][j][3] = 0.f;

    const uint32_t aro = (uint32_t)((wr + (lane & 15)) * 144 + ((lane >> 4) << 3) * 2);
    const uint32_t bro = (uint32_t)((lane & 15) * 272 + (wc + ((lane >> 4) << 3)) * 2);

    for (int it = 0; it < 16; it++) {
        const int cur = it & 1, nx = cur ^ 1;
        __syncthreads();
        if (it < 15) {
            int k0 = (it + 1) * 64;
#pragma unroll
            for (int c = 0; c < 4; c++) {
                int idx = tid + c * 256;
                int r = idx >> 3, ch = idx & 7;
                cpa(sb + ZH[nx] + r * 144 + ch * 16,
                    g_zh + (size_t)(row0 + r) * MM + k0 + ch * 8);
                cpa(sb + ZL[nx] + r * 144 + ch * 16,
                    g_zl + (size_t)(row0 + r) * MM + k0 + ch * 8);
                int kk = idx >> 4, q = idx & 15;
                cpa(sb + UH[nx] + kk * 272 + q * 16,
                    g_Uh + (size_t)(k0 + kk) * MM + col0 + q * 8);
            }
            CPCOMMIT();
            CPWAIT1();
        } else {
            CPWAIT0();
        }
        __syncthreads();

#pragma unroll
        for (int kk = 0; kk < 4; kk++) {
            uint32_t ah0[4], al0[4], ah1[4], al1[4];
            LDSM4(ah0, sb + ZH[cur] + aro + kk * 32);
            LDSM4(al0, sb + ZL[cur] + aro + kk * 32);
            LDSM4(ah1, sb + ZH[cur] + aro + 2304 + kk * 32);
            LDSM4(al1, sb + ZL[cur] + aro + 2304 + kk * 32);
#pragma unroll
            for (int jp = 0; jp < 4; jp++) {
                uint32_t off = (uint32_t)(kk * 4352 + jp * 32);
                uint32_t bh4[4];
                LDSM4T(bh4, sb + UH[cur] + bro + off);
                MMAH(acc[0][2 * jp], ah0, bh4[0], bh4[1]);
                MMAH(acc[0][2 * jp], al0, bh4[0], bh4[1]);
                MMAH(acc[0][2 * jp + 1], ah0, bh4[2], bh4[3]);
                MMAH(acc[0][2 * jp + 1], al0, bh4[2], bh4[3]);
                MMAH(acc[1][2 * jp], ah1, bh4[0], bh4[1]);
                MMAH(acc[1][2 * jp], al1, bh4[0], bh4[1]);
                MMAH(acc[1][2 * jp + 1], ah1, bh4[2], bh4[3]);
                MMAH(acc[1][2 * jp + 1], al1, bh4[2], bh4[3]);
            }
        }
    }

    int r = lane >> 2, cc = (lane & 3) * 2;
#pragma unroll
    for (int rb = 0; rb < 2; rb++) {
        int gr = row0 + wr + rb * 16 + r;
#pragma unroll
        for (int j = 0; j < 8; j++) {
            int gc = col0 + wc + 8 * j + cc;
            float b0v = bo[gc], b1v = bo[gc + 1];
            *(float2*)(out + (size_t)gr * MM + gc) =
                make_float2(acc[rb][j][0] + b0v, acc[rb][j][1] + b1v);
            *(float2*)(out + (size_t)(gr + 8) * MM + gc) =
                make_float2(acc[rb][j][2] + b0v, acc[rb][j][3] + b1v);
        }
    }
}

// ---------------------------------------------------------------------------
// Launch: fork independent precompute onto side streams (graph-capture-legal
// fork/join via events), with full resource cleanup before return.
// ---------------------------------------------------------------------------
extern "C" void kernel_launch(void* const* d_in, const int* in_sizes, int n_in,
                              void* d_out, int out_size) {
    const float* x  = (const float*)d_in[0];
    const float* Wq = (const float*)d_in[1];
    const float* Wk = (const float*)d_in[2];
    const float* Wv = (const float*)d_in[3];
    const float* Wo = (const float*)d_in[4];
    const float* bo = (const float*)d_in[5];
    float* out = (float*)d_out;

    cudaFuncSetAttribute(flashTC, cudaFuncAttributeMaxDynamicSharedMemorySize, FL_SMEM);
    cudaFuncSetAttribute(gemmOutTC, cudaFuncAttributeMaxDynamicSharedMemorySize, GO_SMEM);
    cudaFuncSetAttribute(computeUTC, cudaFuncAttributeMaxDynamicSharedMemorySize, CU_SMEM);

    cudaStream_t sA, sU;
    cudaStreamCreateWithFlags(&sA, cudaStreamNonBlocking);
    cudaStreamCreateWithFlags(&sU, cudaStreamNonBlocking);
    cudaEvent_t e0, eA, eU;
    cudaEventCreateWithFlags(&e0, cudaEventDisableTiming);
    cudaEventCreateWithFlags(&eA, cudaEventDisableTiming);
    cudaEventCreateWithFlags(&eU, cudaEventDisableTiming);

    // fork from the capture-origin (default) stream
    cudaEventRecord(e0, 0);
    cudaStreamWaitEvent(sA, e0, 0);
    cudaStreamWaitEvent(sU, e0, 0);

    // side stream A: A-matrix chain
    computeApart<<<dim3(16, 8), 256, 0, sA>>>(Wq, Wk);
    reduceA<<<256, 256, 0, sA>>>();
    cudaEventRecord(eA, sA);

    // side stream U: U precompute
    computeUTC<<<dim3(16, 16), 256, CU_SMEM, sU>>>(Wv, Wo);
    cudaEventRecord(eU, sU);

    // main stream: x split, then flash (after A), then epilogue (after U)
    splitX<<<4096, 256>>>(x);
    cudaStreamWaitEvent(0, eA, 0);
    flashTC<<<dim3(TT / 64, BB * HH), 128, FL_SMEM>>>();
    cudaStreamWaitEvent(0, eU, 0);
    gemmOutTC<<<dim3(MM / 128, (BB * TT) / 128), 256, GO_SMEM>>>(bo, out);

    // cleanup: both side streams are joined back to the origin stream above,
    // so they are out of capture mode; destroying them here is capture-legal
    // and releases all per-call resources before the harness mem checkpoint.
    cudaEventDestroy(e0);
    cudaEventDestroy(eA);
    cudaEventDestroy(eU);
    cudaStreamDestroy(sA);
    cudaStreamDestroy(sU);
}